// round 1
// baseline (speedup 1.0000x reference)
#include <cuda_runtime.h>

// Problem constants
#define SEQ     4096
#define BATCH   8
#define CH      256
#define M_TOT   (SEQ*BATCH)      // 32768 rows (t-major, b inner)
#define KDIM    512              // virtual K = 2 taps x 256 channels
#define NDIM    512              // Z gate cols [0,256) ++ F gate cols [256,512)
#define NCHUNK  32
#define CHUNK   128              // NCHUNK*CHUNK == SEQ
#define BHTOT   2048             // BATCH*CH

// Scratch (static device globals; runtime allocation is forbidden)
__device__ float g_Z[M_TOT*CH];          // raw Z gate pre-activation [m][h]
__device__ float g_F[M_TOT*CH];          // raw F gate pre-activation [m][h]
__device__ float g_Wp[KDIM*NDIM];        // packed weights, k-major [k][n]
__device__ float g_bias[NDIM];
__device__ float g_cA[NCHUNK*BHTOT];     // per-chunk scan coefficient A
__device__ float g_cB[NCHUNK*BHTOT];     // per-chunk scan offset B
__device__ float g_cH[NCHUNK*BHTOT];     // per-chunk starting hidden state

__device__ __forceinline__ float sigf(float x) {
    return __fdividef(1.0f, 1.0f + __expf(-x));
}

// ---------------------------------------------------------------------------
// Pack Wz/Wf (H, C, K) into k-major B matrix Wp[k][n]:
//   k <  256 : tap 0 (multiplies X[t-1]),  c = k
//   k >= 256 : tap 1 (multiplies X[t]),    c = k-256
//   n <  256 : Wz row n;  n >= 256 : Wf row n-256
// ---------------------------------------------------------------------------
__global__ void pack_w(const float* __restrict__ Wz, const float* __restrict__ bz,
                       const float* __restrict__ Wf, const float* __restrict__ bf) {
    int i = blockIdx.x * 256 + threadIdx.x;
    if (i < KDIM * NDIM) {
        int k = i >> 9, n = i & 511;
        int c   = (k < 256) ? k : (k - 256);
        int tap = (k < 256) ? 0 : 1;
        float v = (n < 256) ? Wz[n * 512 + c * 2 + tap]
                            : Wf[(n - 256) * 512 + c * 2 + tap];
        g_Wp[i] = v;
    }
    if (i < NDIM) {
        g_bias[i] = (i < 256) ? bz[i] : bf[i - 256];
    }
}

// ---------------------------------------------------------------------------
// fp32 GEMM: Out[m,n] = sum_k A2[m,k] * Wp[k,n] + bias[n]
//   A2[m,k] = (k<256) ? X[m-8, k] (0 if m<8)  :  X[m, k-256]
// 128x128 tile, BK=8, 256 threads, 8x8 microtile.
// Writes raw gates to g_Z / g_F.
// ---------------------------------------------------------------------------
#define BM 128
#define BN 128
#define BK 8

__global__ void __launch_bounds__(256)
gemm_conv(const float* __restrict__ X) {
    __shared__ __align__(16) float As[BK][BM];
    __shared__ __align__(16) float Bs[BK][BN];

    const int m0 = blockIdx.y * BM;
    const int n0 = blockIdx.x * BN;
    const int tid = threadIdx.x;
    const int tx = tid & 15;          // 16 col groups
    const int ty = tid >> 4;          // 16 row groups

    // A loader: each thread loads one float4: row ar, k offset ak..ak+3
    const int ar = tid >> 1;
    const int ak = (tid & 1) * 4;
    // B loader: row bk, cols bn..bn+3
    const int bkr = tid >> 5;
    const int bnc = (tid & 31) * 4;

    float acc[8][8];
#pragma unroll
    for (int i = 0; i < 8; i++)
#pragma unroll
        for (int j = 0; j < 8; j++) acc[i][j] = 0.0f;

    for (int kb = 0; kb < KDIM / BK; kb++) {
        const int kbase = kb * BK;
        // ---- load A tile (transposed into As[k][m]) ----
        {
            int kg = kbase + ak;
            int gm; int col;
            if (kg < 256) { gm = m0 + ar - 8; col = kg; }
            else          { gm = m0 + ar;     col = kg - 256; }
            float4 v = make_float4(0.f, 0.f, 0.f, 0.f);
            if (gm >= 0)
                v = *reinterpret_cast<const float4*>(X + gm * CH + col);
            As[ak + 0][ar] = v.x;
            As[ak + 1][ar] = v.y;
            As[ak + 2][ar] = v.z;
            As[ak + 3][ar] = v.w;
        }
        // ---- load B tile ----
        {
            float4 v = *reinterpret_cast<const float4*>(
                g_Wp + (kbase + bkr) * NDIM + n0 + bnc);
            *reinterpret_cast<float4*>(&Bs[bkr][bnc]) = v;
        }
        __syncthreads();

#pragma unroll
        for (int kk = 0; kk < BK; kk++) {
            float a[8], b[8];
            *reinterpret_cast<float4*>(a)     = *reinterpret_cast<const float4*>(&As[kk][ty * 8]);
            *reinterpret_cast<float4*>(a + 4) = *reinterpret_cast<const float4*>(&As[kk][ty * 8 + 4]);
            *reinterpret_cast<float4*>(b)     = *reinterpret_cast<const float4*>(&Bs[kk][tx * 8]);
            *reinterpret_cast<float4*>(b + 4) = *reinterpret_cast<const float4*>(&Bs[kk][tx * 8 + 4]);
#pragma unroll
            for (int i = 0; i < 8; i++)
#pragma unroll
                for (int j = 0; j < 8; j++)
                    acc[i][j] = fmaf(a[i], b[j], acc[i][j]);
        }
        __syncthreads();
    }

    // ---- epilogue: add bias, route to Z or F scratch ----
    float bj[8];
#pragma unroll
    for (int j = 0; j < 8; j++) bj[j] = g_bias[n0 + tx * 8 + j];

    const bool isZ = (n0 < 256);
    const int ncol = isZ ? (n0 + tx * 8) : (n0 - 256 + tx * 8);
    float* dstBase = isZ ? g_Z : g_F;

#pragma unroll
    for (int i = 0; i < 8; i++) {
        int m = m0 + ty * 8 + i;
        float* dst = dstBase + m * CH + ncol;
        float4 v0, v1;
        v0.x = acc[i][0] + bj[0]; v0.y = acc[i][1] + bj[1];
        v0.z = acc[i][2] + bj[2]; v0.w = acc[i][3] + bj[3];
        v1.x = acc[i][4] + bj[4]; v1.y = acc[i][5] + bj[5];
        v1.z = acc[i][6] + bj[6]; v1.w = acc[i][7] + bj[7];
        *reinterpret_cast<float4*>(dst)     = v0;
        *reinterpret_cast<float4*>(dst + 4) = v1;
    }
}

// ---------------------------------------------------------------------------
// Scan pass 1: per (chunk, bh) compute chunk-composed affine (A, B):
//   h_end = A * h_start + B, where per-step h = a*h + b,
//   a = 1 - sigmoid(F), b = sigmoid(F) * quickgelu(Z)
// ---------------------------------------------------------------------------
__global__ void scan1() {
    const int bh = blockIdx.x * 256 + threadIdx.x;
    const int c  = blockIdx.y;
    float A = 1.0f, B = 0.0f;
    const int tbase = c * CHUNK;
#pragma unroll 4
    for (int t = 0; t < CHUNK; t++) {
        int idx = (tbase + t) * BHTOT + bh;
        float fr = g_F[idx];
        float zr = g_Z[idx];
        float f = sigf(fr);
        float z = zr * sigf(1.702f * zr);
        float a = 1.0f - f;
        float b = f * z;
        A *= a;
        B = fmaf(a, B, b);
    }
    g_cA[c * BHTOT + bh] = A;
    g_cB[c * BHTOT + bh] = B;
}

// ---------------------------------------------------------------------------
// Scan pass 2: sequential prefix over the 32 chunks per (b,h) lane.
// Stores chunk-start hidden states; writes final h into h_last tail of out.
// ---------------------------------------------------------------------------
__global__ void scan2(const float* __restrict__ hidden, float* __restrict__ out) {
    const int bh = blockIdx.x * 256 + threadIdx.x;
    float h = hidden[bh];
#pragma unroll
    for (int c = 0; c < NCHUNK; c++) {
        g_cH[c * BHTOT + bh] = h;
        h = fmaf(g_cA[c * BHTOT + bh], h, g_cB[c * BHTOT + bh]);
    }
    out[SEQ * BHTOT + bh] = h;   // h_last (1,B,H) appended after H
}

// ---------------------------------------------------------------------------
// Scan pass 3: replay each chunk from its known start state, write H.
// ---------------------------------------------------------------------------
__global__ void scan3(float* __restrict__ out) {
    const int bh = blockIdx.x * 256 + threadIdx.x;
    const int c  = blockIdx.y;
    float h = g_cH[c * BHTOT + bh];
    const int tbase = c * CHUNK;
#pragma unroll 4
    for (int t = 0; t < CHUNK; t++) {
        int idx = (tbase + t) * BHTOT + bh;
        float fr = g_F[idx];
        float zr = g_Z[idx];
        float f = sigf(fr);
        float z = zr * sigf(1.702f * zr);
        float a = 1.0f - f;
        h = fmaf(a, h, f * z);
        out[idx] = h;
    }
}

// ---------------------------------------------------------------------------
extern "C" void kernel_launch(void* const* d_in, const int* in_sizes, int n_in,
                              void* d_out, int out_size) {
    const float* X      = (const float*)d_in[0];
    const float* hidden = (const float*)d_in[1];
    const float* Wz     = (const float*)d_in[2];
    const float* bz     = (const float*)d_in[3];
    const float* Wf     = (const float*)d_in[4];
    const float* bf     = (const float*)d_in[5];
    float* out = (float*)d_out;

    pack_w<<<(KDIM * NDIM + 255) / 256, 256>>>(Wz, bz, Wf, bf);

    dim3 ggrid(NDIM / BN, M_TOT / BM);
    gemm_conv<<<ggrid, 256>>>(X);

    scan1<<<dim3(BHTOT / 256, NCHUNK), 256>>>();
    scan2<<<BHTOT / 256, 256>>>(hidden, out);
    scan3<<<dim3(BHTOT / 256, NCHUNK), 256>>>(out);
}

// round 3
// speedup vs baseline: 2.2213x; 2.2213x over previous
#include <cuda_runtime.h>
#include <cuda_bf16.h>
#include <cstdint>

// Problem constants
#define SEQ     4096
#define BATCH   8
#define CH      256
#define M_TOT   (SEQ*BATCH)      // 32768 rows (t-major, b inner)
#define KDIM    512              // virtual K = 2 taps x 256 channels
#define NDIM    512              // Z cols [0,256) ++ F cols [256,512)
#define NCHUNK  32
#define CHUNK   128
#define BHTOT   2048             // BATCH*CH

// Scratch (static device globals; runtime allocation forbidden)
__device__ float g_Z[M_TOT*CH];
__device__ float g_F[M_TOT*CH];
__device__ __nv_bfloat16 g_Xh[M_TOT*CH];
__device__ __nv_bfloat16 g_Xl[M_TOT*CH];
__device__ __nv_bfloat16 g_Wh[NDIM*KDIM];   // [n][k] K-major
__device__ __nv_bfloat16 g_Wl[NDIM*KDIM];
__device__ float g_biasf[NDIM];
__device__ float g_cA[NCHUNK*BHTOT];
__device__ float g_cB[NCHUNK*BHTOT];
__device__ float g_cH[NCHUNK*BHTOT];

__device__ __forceinline__ float sigf(float x) {
    return __fdividef(1.0f, 1.0f + __expf(-x));
}

__device__ __forceinline__ uint32_t smem_u32(const void* p) {
    return (uint32_t)__cvta_generic_to_shared(p);
}

// ---------------------------------------------------------------------------
// Portable (non-103a) primitives: cp.async, ldmatrix, mma.sync bf16
// ---------------------------------------------------------------------------
__device__ __forceinline__ void cp_async16(uint32_t dst, const void* src, uint32_t sz) {
    asm volatile("cp.async.cg.shared.global [%0], [%1], 16, %2;"
                 :: "r"(dst), "l"(src), "r"(sz) : "memory");
}
#define CP_COMMIT() asm volatile("cp.async.commit_group;" ::: "memory")
#define CP_WAIT(n)  asm volatile("cp.async.wait_group %0;" :: "n"(n) : "memory")

__device__ __forceinline__ void ldsm_x4(uint32_t* r, uint32_t addr) {
    asm volatile("ldmatrix.sync.aligned.m8n8.x4.shared.b16 {%0,%1,%2,%3}, [%4];"
                 : "=r"(r[0]), "=r"(r[1]), "=r"(r[2]), "=r"(r[3]) : "r"(addr));
}
__device__ __forceinline__ void ldsm_x2(uint32_t* r, uint32_t addr) {
    asm volatile("ldmatrix.sync.aligned.m8n8.x2.shared.b16 {%0,%1}, [%2];"
                 : "=r"(r[0]), "=r"(r[1]) : "r"(addr));
}
__device__ __forceinline__ void mma_bf16(float* d, const uint32_t* a, const uint32_t* b) {
    asm volatile(
        "mma.sync.aligned.m16n8k16.row.col.f32.bf16.bf16.f32 "
        "{%0,%1,%2,%3}, {%4,%5,%6,%7}, {%8,%9}, {%0,%1,%2,%3};"
        : "+f"(d[0]), "+f"(d[1]), "+f"(d[2]), "+f"(d[3])
        : "r"(a[0]), "r"(a[1]), "r"(a[2]), "r"(a[3]), "r"(b[0]), "r"(b[1]));
}

// ---------------------------------------------------------------------------
// Convert X -> bf16 hi/lo split
// ---------------------------------------------------------------------------
__global__ void convert_x(const float* __restrict__ X) {
    int i = blockIdx.x * 256 + threadIdx.x;           // group of 4 floats
    float4 v = reinterpret_cast<const float4*>(X)[i];
    __nv_bfloat16 h0 = __float2bfloat16_rn(v.x);
    __nv_bfloat16 h1 = __float2bfloat16_rn(v.y);
    __nv_bfloat16 h2 = __float2bfloat16_rn(v.z);
    __nv_bfloat16 h3 = __float2bfloat16_rn(v.w);
    __nv_bfloat16 l0 = __float2bfloat16_rn(v.x - __bfloat162float(h0));
    __nv_bfloat16 l1 = __float2bfloat16_rn(v.y - __bfloat162float(h1));
    __nv_bfloat16 l2 = __float2bfloat16_rn(v.z - __bfloat162float(h2));
    __nv_bfloat16 l3 = __float2bfloat16_rn(v.w - __bfloat162float(h3));
    __nv_bfloat162* ph = reinterpret_cast<__nv_bfloat162*>(g_Xh);
    __nv_bfloat162* pl = reinterpret_cast<__nv_bfloat162*>(g_Xl);
    ph[i * 2 + 0] = __nv_bfloat162(h0, h1);
    ph[i * 2 + 1] = __nv_bfloat162(h2, h3);
    pl[i * 2 + 0] = __nv_bfloat162(l0, l1);
    pl[i * 2 + 1] = __nv_bfloat162(l2, l3);
}

// ---------------------------------------------------------------------------
// Pack weights: W[n][k] (K-major). n<256 -> Wz row n, else Wf row n-256.
// k<256: tap0 (X[t-1]), c=k ; k>=256: tap1 (X[t]), c=k-256.
// ---------------------------------------------------------------------------
__global__ void pack_w(const float* __restrict__ Wz, const float* __restrict__ bz,
                       const float* __restrict__ Wf, const float* __restrict__ bf) {
    int i = blockIdx.x * 256 + threadIdx.x;
    if (i < NDIM * KDIM) {
        int n = i >> 9, k = i & 511;
        int c   = (k < 256) ? k : (k - 256);
        int tap = (k < 256) ? 0 : 1;
        float v = (n < 256) ? Wz[n * 512 + c * 2 + tap]
                            : Wf[(n - 256) * 512 + c * 2 + tap];
        __nv_bfloat16 h = __float2bfloat16_rn(v);
        g_Wh[i] = h;
        g_Wl[i] = __float2bfloat16_rn(v - __bfloat162float(h));
    }
    if (i < NDIM) g_biasf[i] = (i < 256) ? bz[i] : bf[i - 256];
}

// ---------------------------------------------------------------------------
// HMMA GEMM: C[m,n] = sum_k A[m,k]*W[n,k] + bias, split bf16:
//   C = Ah*Wh + Ah*Wl + Al*Wh   (fp32 accumulate)
// CTA tile 128(M) x 128(N), K staged 32 wide, cp.async double buffer.
// grid = (4 n-tiles, 256 m-tiles), 256 threads (8 warps of 64x32).
// SMEM rows padded: 32 bf16 (64B) stored with 80B stride (conflict-free ldsm).
// ---------------------------------------------------------------------------
#define LDS_ROW  80
#define TILE_B   (128*LDS_ROW)         // 10240 bytes per subtile
#define STAGE_B  (4*TILE_B)            // Ah, Al, Bh, Bl
#define SMEM_GEMM (2*STAGE_B)          // 81920 bytes

__global__ void __launch_bounds__(256, 2)
gemm_mma() {
    extern __shared__ char smem[];
    const uint32_t sb = smem_u32(smem);
    const int tid  = threadIdx.x;
    const int lane = tid & 31;
    const int wid  = tid >> 5;
    const int mwarp = wid & 1;          // 2 warps along M (64 rows each)
    const int nwarp = wid >> 1;         // 4 warps along N (32 cols each)
    const int m0 = blockIdx.y * 128;
    const int n0 = blockIdx.x * 128;

    // ---- stage loader (8 x cp.async 16B per thread) ----
    auto load_stage = [&](int s, int buf) {
        const int kb = s * 32;
        const int tap = (kb < 256) ? 0 : 1;
        const int xcol = kb - tap * 256;
        const int rowoff = tap ? 0 : -8;
        const uint32_t base = sb + buf * STAGE_B;
#pragma unroll
        for (int q = 0; q < 2; q++) {
            int id = tid * 2 + q;          // 0..511
            int row = id >> 2, c = id & 3;
            uint32_t doff = row * LDS_ROW + c * 16;
            // A hi / A lo
            int gm = m0 + row + rowoff;
            uint32_t sz = (gm >= 0) ? 16u : 0u;
            int gmc = (gm >= 0) ? gm : 0;
            cp_async16(base + doff,            g_Xh + gmc * CH + xcol + c * 8, sz);
            cp_async16(base + TILE_B + doff,   g_Xl + gmc * CH + xcol + c * 8, sz);
            // B hi / B lo
            int gn = n0 + row;
            cp_async16(base + 2 * TILE_B + doff, g_Wh + gn * KDIM + kb + c * 8, 16u);
            cp_async16(base + 3 * TILE_B + doff, g_Wl + gn * KDIM + kb + c * 8, 16u);
        }
    };

    float acc[4][4][4];
#pragma unroll
    for (int i = 0; i < 4; i++)
#pragma unroll
        for (int j = 0; j < 4; j++)
#pragma unroll
            for (int q = 0; q < 4; q++) acc[i][j][q] = 0.0f;

    // ldmatrix intra-tile offsets
    const uint32_t a_off = (mwarp * 64 + (lane & 15)) * LDS_ROW + (lane >> 4) * 16;
    const uint32_t b_off = (nwarp * 32 + (lane & 7)) * LDS_ROW + ((lane >> 3) & 1) * 16;

    load_stage(0, 0); CP_COMMIT();
    load_stage(1, 1); CP_COMMIT();

    for (int s = 0; s < 16; s++) {
        if (s < 15) { CP_WAIT(1); } else { CP_WAIT(0); }
        __syncthreads();

        const uint32_t base = sb + (s & 1) * STAGE_B;
#pragma unroll
        for (int kk = 0; kk < 2; kk++) {
            uint32_t aH[4][4], aL[4][4];
#pragma unroll
            for (int mf = 0; mf < 4; mf++) {
                uint32_t ao = a_off + mf * 16 * LDS_ROW + kk * 32;
                ldsm_x4(aH[mf], base + ao);
                ldsm_x4(aL[mf], base + TILE_B + ao);
            }
#pragma unroll
            for (int nf = 0; nf < 4; nf++) {
                uint32_t bo = b_off + nf * 8 * LDS_ROW + kk * 32;
                uint32_t bh[2], bl[2];
                ldsm_x2(bh, base + 2 * TILE_B + bo);
                ldsm_x2(bl, base + 3 * TILE_B + bo);
#pragma unroll
                for (int mf = 0; mf < 4; mf++) {
                    mma_bf16(acc[mf][nf], aH[mf], bh);
                    mma_bf16(acc[mf][nf], aH[mf], bl);
                    mma_bf16(acc[mf][nf], aL[mf], bh);
                }
            }
        }
        __syncthreads();
        if (s + 2 < 16) { load_stage(s + 2, s & 1); CP_COMMIT(); }
    }

    // ---- epilogue: +bias, write raw gates to g_Z / g_F ----
    const int g4  = lane >> 2;            // 0..7
    const int t4  = lane & 3;             // 0..3
    const bool isF = (n0 >= 256);
    float* dstBase = isF ? g_F : g_Z;
    const int nloc0 = n0 - (isF ? 256 : 0) + nwarp * 32 + t4 * 2;

#pragma unroll
    for (int nf = 0; nf < 4; nf++) {
        const int ncol = nloc0 + nf * 8;
        const float b0 = g_biasf[(isF ? 256 : 0) + ncol];
        const float b1 = g_biasf[(isF ? 256 : 0) + ncol + 1];
#pragma unroll
        for (int mf = 0; mf < 4; mf++) {
            const int m = m0 + mwarp * 64 + mf * 16 + g4;
            float2 v0 = make_float2(acc[mf][nf][0] + b0, acc[mf][nf][1] + b1);
            float2 v1 = make_float2(acc[mf][nf][2] + b0, acc[mf][nf][3] + b1);
            *reinterpret_cast<float2*>(dstBase + m * CH + ncol)       = v0;
            *reinterpret_cast<float2*>(dstBase + (m + 8) * CH + ncol) = v1;
        }
    }
}

// ---------------------------------------------------------------------------
// Scan pass 1: per (chunk, bh), compose chunk affine (A, B)
// ---------------------------------------------------------------------------
__global__ void scan1() {
    const int bh = blockIdx.x * 256 + threadIdx.x;
    const int c  = blockIdx.y;
    float A = 1.0f, B = 0.0f;
    const int tbase = c * CHUNK;
#pragma unroll 4
    for (int t = 0; t < CHUNK; t++) {
        int idx = (tbase + t) * BHTOT + bh;
        float fr = g_F[idx];
        float zr = g_Z[idx];
        float f = sigf(fr);
        float z = zr * sigf(1.702f * zr);
        float a = 1.0f - f;
        A *= a;
        B = fmaf(a, B, f * z);
    }
    g_cA[c * BHTOT + bh] = A;
    g_cB[c * BHTOT + bh] = B;
}

// ---------------------------------------------------------------------------
// Scan pass 2: prefix over 32 chunks; preload all coeffs (latency fix)
// ---------------------------------------------------------------------------
__global__ void scan2(const float* __restrict__ hidden, float* __restrict__ out) {
    const int bh = blockIdx.x * 256 + threadIdx.x;
    float A[NCHUNK], Bv[NCHUNK];
#pragma unroll
    for (int c = 0; c < NCHUNK; c++) {
        A[c]  = g_cA[c * BHTOT + bh];
        Bv[c] = g_cB[c * BHTOT + bh];
    }
    float h = hidden[bh];
#pragma unroll
    for (int c = 0; c < NCHUNK; c++) {
        g_cH[c * BHTOT + bh] = h;
        h = fmaf(A[c], h, Bv[c]);
    }
    out[SEQ * BHTOT + bh] = h;   // h_last
}

// ---------------------------------------------------------------------------
// Scan pass 3: replay each chunk, write H
// ---------------------------------------------------------------------------
__global__ void scan3(float* __restrict__ out) {
    const int bh = blockIdx.x * 256 + threadIdx.x;
    const int c  = blockIdx.y;
    float h = g_cH[c * BHTOT + bh];
    const int tbase = c * CHUNK;
#pragma unroll 4
    for (int t = 0; t < CHUNK; t++) {
        int idx = (tbase + t) * BHTOT + bh;
        float fr = g_F[idx];
        float zr = g_Z[idx];
        float f = sigf(fr);
        float z = zr * sigf(1.702f * zr);
        h = fmaf(1.0f - f, h, f * z);
        out[idx] = h;
    }
}

// ---------------------------------------------------------------------------
extern "C" void kernel_launch(void* const* d_in, const int* in_sizes, int n_in,
                              void* d_out, int out_size) {
    const float* X      = (const float*)d_in[0];
    const float* hidden = (const float*)d_in[1];
    const float* Wz     = (const float*)d_in[2];
    const float* bz     = (const float*)d_in[3];
    const float* Wf     = (const float*)d_in[4];
    const float* bf     = (const float*)d_in[5];
    float* out = (float*)d_out;

    convert_x<<<M_TOT * CH / 4 / 256, 256>>>(X);
    pack_w<<<(NDIM * KDIM + 255) / 256, 256>>>(Wz, bz, Wf, bf);

    cudaFuncSetAttribute(gemm_mma, cudaFuncAttributeMaxDynamicSharedMemorySize, SMEM_GEMM);
    gemm_mma<<<dim3(4, 256), 256, SMEM_GEMM>>>();

    scan1<<<dim3(BHTOT / 256, NCHUNK), 256>>>();
    scan2<<<BHTOT / 256, 256>>>(hidden, out);
    scan3<<<dim3(BHTOT / 256, NCHUNK), 256>>>(out);
}

// round 4
// speedup vs baseline: 3.0119x; 1.3559x over previous
#include <cuda_runtime.h>
#include <cuda_fp16.h>
#include <cstdint>

// Problem constants
#define SEQ     4096
#define BATCH   8
#define CH      256
#define M_TOT   (SEQ*BATCH)      // 32768 rows (t-major, b inner)
#define KDIM    512              // virtual K = 2 taps x 256 channels
#define NDIM    512              // Z cols [0,256) ++ F cols [256,512)
#define NCHUNK  128
#define CHUNK   32               // NCHUNK*CHUNK == SEQ
#define BHTOT   2048             // BATCH*CH

// Scratch (static device globals; runtime allocation forbidden)
__device__ float g_Z[M_TOT*CH];
__device__ float g_F[M_TOT*CH];
__device__ __half g_Xh[M_TOT*CH];
__device__ __half g_Xl[M_TOT*CH];
__device__ __half g_Wh[NDIM*KDIM];          // [n][k] K-major, fp16
__device__ float g_biasf[NDIM];
__device__ float g_cA[NCHUNK*BHTOT];
__device__ float g_cB[NCHUNK*BHTOT];
__device__ float g_cH[NCHUNK*BHTOT];

__device__ __forceinline__ float sigf(float x) {
    return __fdividef(1.0f, 1.0f + __expf(-x));
}

__device__ __forceinline__ uint32_t smem_u32(const void* p) {
    return (uint32_t)__cvta_generic_to_shared(p);
}

// ---------------------------------------------------------------------------
// Portable primitives: cp.async, ldmatrix, mma.sync fp16
// ---------------------------------------------------------------------------
__device__ __forceinline__ void cp_async16(uint32_t dst, const void* src, uint32_t sz) {
    asm volatile("cp.async.cg.shared.global [%0], [%1], 16, %2;"
                 :: "r"(dst), "l"(src), "r"(sz) : "memory");
}
#define CP_COMMIT() asm volatile("cp.async.commit_group;" ::: "memory")
#define CP_WAIT(n)  asm volatile("cp.async.wait_group %0;" :: "n"(n) : "memory")

__device__ __forceinline__ void ldsm_x4(uint32_t* r, uint32_t addr) {
    asm volatile("ldmatrix.sync.aligned.m8n8.x4.shared.b16 {%0,%1,%2,%3}, [%4];"
                 : "=r"(r[0]), "=r"(r[1]), "=r"(r[2]), "=r"(r[3]) : "r"(addr));
}
__device__ __forceinline__ void ldsm_x2(uint32_t* r, uint32_t addr) {
    asm volatile("ldmatrix.sync.aligned.m8n8.x2.shared.b16 {%0,%1}, [%2];"
                 : "=r"(r[0]), "=r"(r[1]) : "r"(addr));
}
__device__ __forceinline__ void mma_f16(float* d, const uint32_t* a, const uint32_t* b) {
    asm volatile(
        "mma.sync.aligned.m16n8k16.row.col.f32.f16.f16.f32 "
        "{%0,%1,%2,%3}, {%4,%5,%6,%7}, {%8,%9}, {%0,%1,%2,%3};"
        : "+f"(d[0]), "+f"(d[1]), "+f"(d[2]), "+f"(d[3])
        : "r"(a[0]), "r"(a[1]), "r"(a[2]), "r"(a[3]), "r"(b[0]), "r"(b[1]));
}

// ---------------------------------------------------------------------------
// Convert X -> fp16 hi/lo split
// ---------------------------------------------------------------------------
__global__ void convert_x(const float* __restrict__ X) {
    int i = blockIdx.x * 256 + threadIdx.x;           // group of 4 floats
    float4 v = reinterpret_cast<const float4*>(X)[i];
    __half h0 = __float2half_rn(v.x);
    __half h1 = __float2half_rn(v.y);
    __half h2 = __float2half_rn(v.z);
    __half h3 = __float2half_rn(v.w);
    __half l0 = __float2half_rn(v.x - __half2float(h0));
    __half l1 = __float2half_rn(v.y - __half2float(h1));
    __half l2 = __float2half_rn(v.z - __half2float(h2));
    __half l3 = __float2half_rn(v.w - __half2float(h3));
    __half2* ph = reinterpret_cast<__half2*>(g_Xh);
    __half2* pl = reinterpret_cast<__half2*>(g_Xl);
    ph[i * 2 + 0] = __half2(h0, h1);
    ph[i * 2 + 1] = __half2(h2, h3);
    pl[i * 2 + 0] = __half2(l0, l1);
    pl[i * 2 + 1] = __half2(l2, l3);
}

// ---------------------------------------------------------------------------
// Pack weights: W[n][k] (K-major) fp16. n<256 -> Wz row n, else Wf row n-256.
// k<256: tap0 (X[t-1]), c=k ; k>=256: tap1 (X[t]), c=k-256.
// ---------------------------------------------------------------------------
__global__ void pack_w(const float* __restrict__ Wz, const float* __restrict__ bz,
                       const float* __restrict__ Wf, const float* __restrict__ bf) {
    int i = blockIdx.x * 256 + threadIdx.x;
    if (i < NDIM * KDIM) {
        int n = i >> 9, k = i & 511;
        int c   = (k < 256) ? k : (k - 256);
        int tap = (k < 256) ? 0 : 1;
        float v = (n < 256) ? Wz[n * 512 + c * 2 + tap]
                            : Wf[(n - 256) * 512 + c * 2 + tap];
        g_Wh[i] = __float2half_rn(v);
    }
    if (i < NDIM) g_biasf[i] = (i < 256) ? bz[i] : bf[i - 256];
}

// ---------------------------------------------------------------------------
// HMMA GEMM: C[m,n] = sum_k (Ah+Al)[m,k]*W[n,k] + bias  (fp16 in, fp32 acc)
// CTA tile 128(M) x 256(N), K staged 32 wide, 4-stage cp.async ring.
// grid = (2 n-tiles, 256 m-tiles), 256 threads = 8 warps (2M x 4N, 64x64 each).
// SMEM rows padded: 32 fp16 (64B) at 80B stride (conflict-free ldmatrix).
// ---------------------------------------------------------------------------
#define LDS_ROW  80
#define A_TILE   (128*LDS_ROW)         // 10240 B
#define B_TILE   (256*LDS_ROW)         // 20480 B
#define STAGE_B  (2*A_TILE + B_TILE)   // Ah, Al, B : 40960 B
#define NSTAGE   4
#define SMEM_GEMM (NSTAGE*STAGE_B)     // 163840 B

__global__ void __launch_bounds__(256, 1)
gemm_mma() {
    extern __shared__ char smem[];
    const uint32_t sb = smem_u32(smem);
    const int tid  = threadIdx.x;
    const int lane = tid & 31;
    const int wid  = tid >> 5;
    const int mwarp = wid & 1;          // 2 warps along M (64 rows each)
    const int nwarp = wid >> 1;         // 4 warps along N (64 cols each)
    const int m0 = blockIdx.y * 128;
    const int n0 = blockIdx.x * 256;

    auto load_stage = [&](int s) {
        const int kb = s * 32;
        const int tap = (kb < 256) ? 0 : 1;
        const int xcol = kb - tap * 256;
        const int rowoff = tap ? 0 : -8;
        const uint32_t base = sb + (s & (NSTAGE - 1)) * STAGE_B;
#pragma unroll
        for (int q = 0; q < 8; q++) {
            const int idx = q * 256 + tid;
            if (q < 2) {                 // Ah : ids 0..511
                int row = idx >> 2, c = idx & 3;
                int gm = m0 + row + rowoff;
                int gmc = (gm >= 0) ? gm : 0;
                cp_async16(base + row * LDS_ROW + c * 16,
                           g_Xh + gmc * CH + xcol + c * 8, (gm >= 0) ? 16u : 0u);
            } else if (q < 4) {          // Al : ids 512..1023
                int i2 = idx - 512;
                int row = i2 >> 2, c = i2 & 3;
                int gm = m0 + row + rowoff;
                int gmc = (gm >= 0) ? gm : 0;
                cp_async16(base + A_TILE + row * LDS_ROW + c * 16,
                           g_Xl + gmc * CH + xcol + c * 8, (gm >= 0) ? 16u : 0u);
            } else {                     // B : ids 0..1023
                int i2 = idx - 1024;
                int row = i2 >> 2, c = i2 & 3;
                cp_async16(base + 2 * A_TILE + row * LDS_ROW + c * 16,
                           g_Wh + (n0 + row) * KDIM + kb + c * 8, 16u);
            }
        }
    };

    float acc[4][8][4];
#pragma unroll
    for (int i = 0; i < 4; i++)
#pragma unroll
        for (int j = 0; j < 8; j++)
#pragma unroll
            for (int q = 0; q < 4; q++) acc[i][j][q] = 0.0f;

    const uint32_t a_off = (mwarp * 64 + (lane & 15)) * LDS_ROW + (lane >> 4) * 16;
    const uint32_t b_off = (nwarp * 64 + (lane & 7)) * LDS_ROW + ((lane >> 3) & 1) * 16;

    load_stage(0); CP_COMMIT();
    load_stage(1); CP_COMMIT();
    load_stage(2); CP_COMMIT();

    for (int s = 0; s < 16; s++) {
        CP_WAIT(2);                 // stage s resident (3 groups always in flight)
        __syncthreads();            // all warps done reading buffer (s-1)&3
        if (s + 3 < 16) load_stage(s + 3);
        CP_COMMIT();                // empty group when no loads -> WAIT(2) stays exact

        const uint32_t base = sb + (s & (NSTAGE - 1)) * STAGE_B;
#pragma unroll
        for (int kk = 0; kk < 2; kk++) {
            uint32_t aH[4][4], aL[4][4];
#pragma unroll
            for (int mf = 0; mf < 4; mf++) {
                uint32_t ao = a_off + mf * 16 * LDS_ROW + kk * 32;
                ldsm_x4(aH[mf], base + ao);
                ldsm_x4(aL[mf], base + A_TILE + ao);
            }
#pragma unroll
            for (int nf = 0; nf < 8; nf++) {
                uint32_t b[2];
                ldsm_x2(b, base + 2 * A_TILE + b_off + nf * 8 * LDS_ROW + kk * 32);
#pragma unroll
                for (int mf = 0; mf < 4; mf++) {
                    mma_f16(acc[mf][nf], aH[mf], b);
                    mma_f16(acc[mf][nf], aL[mf], b);
                }
            }
        }
    }

    // ---- epilogue: +bias, write raw gates to g_Z / g_F ----
    const int g4  = lane >> 2;            // 0..7 (row within 8)
    const int t4  = lane & 3;             // 0..3 (col pair)
    const bool isF = (n0 >= 256);
    float* dstBase = isF ? g_F : g_Z;
    const int nbias0 = n0 + nwarp * 64 + t4 * 2;
    const int nloc0  = nbias0 - (isF ? 256 : 0);

#pragma unroll
    for (int nf = 0; nf < 8; nf++) {
        const int ncol = nloc0 + nf * 8;
        const float b0 = g_biasf[nbias0 + nf * 8];
        const float b1 = g_biasf[nbias0 + nf * 8 + 1];
#pragma unroll
        for (int mf = 0; mf < 4; mf++) {
            const int m = m0 + mwarp * 64 + mf * 16 + g4;
            float2 v0 = make_float2(acc[mf][nf][0] + b0, acc[mf][nf][1] + b1);
            float2 v1 = make_float2(acc[mf][nf][2] + b0, acc[mf][nf][3] + b1);
            *reinterpret_cast<float2*>(dstBase + m * CH + ncol)       = v0;
            *reinterpret_cast<float2*>(dstBase + (m + 8) * CH + ncol) = v1;
        }
    }
}

// ---------------------------------------------------------------------------
// Scan pass 1: per (chunk, bh), compose chunk affine (A, B)
// ---------------------------------------------------------------------------
__global__ void scan1() {
    const int bh = blockIdx.x * 256 + threadIdx.x;
    const int c  = blockIdx.y;
    float A = 1.0f, B = 0.0f;
    const int tbase = c * CHUNK;
#pragma unroll 4
    for (int t = 0; t < CHUNK; t++) {
        int idx = (tbase + t) * BHTOT + bh;
        float fr = g_F[idx];
        float zr = g_Z[idx];
        float f = sigf(fr);
        float z = zr * sigf(1.702f * zr);
        float a = 1.0f - f;
        A *= a;
        B = fmaf(a, B, f * z);
    }
    g_cA[c * BHTOT + bh] = A;
    g_cB[c * BHTOT + bh] = B;
}

// ---------------------------------------------------------------------------
// Scan pass 2: prefix over 128 chunks, 16-wide prefetch batches
// ---------------------------------------------------------------------------
__global__ void scan2(const float* __restrict__ hidden, float* __restrict__ out) {
    const int bh = blockIdx.x * 256 + threadIdx.x;
    float h = hidden[bh];
    for (int cb = 0; cb < NCHUNK; cb += 16) {
        float A[16], Bv[16];
#pragma unroll
        for (int i = 0; i < 16; i++) {
            A[i]  = g_cA[(cb + i) * BHTOT + bh];
            Bv[i] = g_cB[(cb + i) * BHTOT + bh];
        }
#pragma unroll
        for (int i = 0; i < 16; i++) {
            g_cH[(cb + i) * BHTOT + bh] = h;
            h = fmaf(A[i], h, Bv[i]);
        }
    }
    out[SEQ * BHTOT + bh] = h;   // h_last
}

// ---------------------------------------------------------------------------
// Scan pass 3: replay each chunk, write H
// ---------------------------------------------------------------------------
__global__ void scan3(float* __restrict__ out) {
    const int bh = blockIdx.x * 256 + threadIdx.x;
    const int c  = blockIdx.y;
    float h = g_cH[c * BHTOT + bh];
    const int tbase = c * CHUNK;
#pragma unroll 4
    for (int t = 0; t < CHUNK; t++) {
        int idx = (tbase + t) * BHTOT + bh;
        float fr = g_F[idx];
        float zr = g_Z[idx];
        float f = sigf(fr);
        float z = zr * sigf(1.702f * zr);
        h = fmaf(1.0f - f, h, f * z);
        out[idx] = h;
    }
}

// ---------------------------------------------------------------------------
extern "C" void kernel_launch(void* const* d_in, const int* in_sizes, int n_in,
                              void* d_out, int out_size) {
    const float* X      = (const float*)d_in[0];
    const float* hidden = (const float*)d_in[1];
    const float* Wz     = (const float*)d_in[2];
    const float* bz     = (const float*)d_in[3];
    const float* Wf     = (const float*)d_in[4];
    const float* bf     = (const float*)d_in[5];
    float* out = (float*)d_out;

    convert_x<<<M_TOT * CH / 4 / 256, 256>>>(X);
    pack_w<<<(NDIM * KDIM + 255) / 256, 256>>>(Wz, bz, Wf, bf);

    cudaFuncSetAttribute(gemm_mma, cudaFuncAttributeMaxDynamicSharedMemorySize, SMEM_GEMM);
    gemm_mma<<<dim3(2, 256), 256, SMEM_GEMM>>>();

    scan1<<<dim3(BHTOT / 256, NCHUNK), 256>>>();
    scan2<<<BHTOT / 256, 256>>>(hidden, out);
    scan3<<<dim3(BHTOT / 256, NCHUNK), 256>>>(out);
}

// round 5
// speedup vs baseline: 4.0645x; 1.3495x over previous
#include <cuda_runtime.h>
#include <cuda_fp16.h>
#include <cstdint>

// Problem constants
#define SEQ     4096
#define BATCH   8
#define CH      256
#define M_TOT   (SEQ*BATCH)      // 32768 rows (t-major, b inner)
#define KDIM    512              // virtual K = 2 taps x 256 channels
#define NDIM    512              // Z cols [0,256) ++ F cols [256,512)
#define NCHUNK  128
#define CHUNK   32               // NCHUNK*CHUNK == SEQ
#define BHTOT   2048             // BATCH*CH

// Scratch (static device globals; runtime allocation forbidden)
__device__ float g_Z[M_TOT*CH];             // post-activation: qgelu(Z)
__device__ float g_F[M_TOT*CH];             // post-activation: sigmoid(F)
__device__ __half g_Xh[M_TOT*CH];
__device__ __half g_Wh[NDIM*KDIM];          // [n][k] K-major, fp16
__device__ float g_biasf[NDIM];
__device__ float g_cA[NCHUNK*BHTOT];
__device__ float g_cB[NCHUNK*BHTOT];
__device__ float g_cH[NCHUNK*BHTOT];

__device__ __forceinline__ float sigf(float x) {
    return __fdividef(1.0f, 1.0f + __expf(-x));
}

__device__ __forceinline__ uint32_t smem_u32(const void* p) {
    return (uint32_t)__cvta_generic_to_shared(p);
}

// ---------------------------------------------------------------------------
// Portable primitives: cp.async, ldmatrix, mma.sync fp16
// ---------------------------------------------------------------------------
__device__ __forceinline__ void cp_async16(uint32_t dst, const void* src, uint32_t sz) {
    asm volatile("cp.async.cg.shared.global [%0], [%1], 16, %2;"
                 :: "r"(dst), "l"(src), "r"(sz) : "memory");
}
#define CP_COMMIT() asm volatile("cp.async.commit_group;" ::: "memory")
#define CP_WAIT(n)  asm volatile("cp.async.wait_group %0;" :: "n"(n) : "memory")

__device__ __forceinline__ void ldsm_x4(uint32_t* r, uint32_t addr) {
    asm volatile("ldmatrix.sync.aligned.m8n8.x4.shared.b16 {%0,%1,%2,%3}, [%4];"
                 : "=r"(r[0]), "=r"(r[1]), "=r"(r[2]), "=r"(r[3]) : "r"(addr));
}
__device__ __forceinline__ void ldsm_x2(uint32_t* r, uint32_t addr) {
    asm volatile("ldmatrix.sync.aligned.m8n8.x2.shared.b16 {%0,%1}, [%2];"
                 : "=r"(r[0]), "=r"(r[1]) : "r"(addr));
}
__device__ __forceinline__ void mma_f16(float* d, const uint32_t* a, const uint32_t* b) {
    asm volatile(
        "mma.sync.aligned.m16n8k16.row.col.f32.f16.f16.f32 "
        "{%0,%1,%2,%3}, {%4,%5,%6,%7}, {%8,%9}, {%0,%1,%2,%3};"
        : "+f"(d[0]), "+f"(d[1]), "+f"(d[2]), "+f"(d[3])
        : "r"(a[0]), "r"(a[1]), "r"(a[2]), "r"(a[3]), "r"(b[0]), "r"(b[1]));
}

// ---------------------------------------------------------------------------
// Convert X -> fp16
// ---------------------------------------------------------------------------
__global__ void convert_x(const float* __restrict__ X) {
    int i = blockIdx.x * 256 + threadIdx.x;           // group of 4 floats
    float4 v = reinterpret_cast<const float4*>(X)[i];
    __half2* ph = reinterpret_cast<__half2*>(g_Xh);
    ph[i * 2 + 0] = __half2(__float2half_rn(v.x), __float2half_rn(v.y));
    ph[i * 2 + 1] = __half2(__float2half_rn(v.z), __float2half_rn(v.w));
}

// ---------------------------------------------------------------------------
// Pack weights: W[n][k] (K-major) fp16. n<256 -> Wz row n, else Wf row n-256.
// k<256: tap0 (X[t-1]), c=k ; k>=256: tap1 (X[t]), c=k-256.
// ---------------------------------------------------------------------------
__global__ void pack_w(const float* __restrict__ Wz, const float* __restrict__ bz,
                       const float* __restrict__ Wf, const float* __restrict__ bf) {
    int i = blockIdx.x * 256 + threadIdx.x;
    if (i < NDIM * KDIM) {
        int n = i >> 9, k = i & 511;
        int c   = (k < 256) ? k : (k - 256);
        int tap = (k < 256) ? 0 : 1;
        float v = (n < 256) ? Wz[n * 512 + c * 2 + tap]
                            : Wf[(n - 256) * 512 + c * 2 + tap];
        g_Wh[i] = __float2half_rn(v);
    }
    if (i < NDIM) g_biasf[i] = (i < 256) ? bz[i] : bf[i - 256];
}

// ---------------------------------------------------------------------------
// HMMA GEMM: C[m,n] = sum_k A[m,k]*W[n,k] + bias  (fp16 in, fp32 acc)
// CTA tile 128(M) x 256(N), K staged 32 wide, 4-stage cp.async ring.
// grid = (2 n-tiles, 256 m-tiles), 256 threads = 8 warps (2M x 4N, 64x64 each).
// Epilogue applies the gate activation (qgelu for Z CTAs, sigmoid for F CTAs).
// SMEM rows padded: 32 fp16 (64B) at 80B stride (conflict-free ldmatrix).
// ---------------------------------------------------------------------------
#define LDS_ROW  80
#define A_TILE   (128*LDS_ROW)         // 10240 B
#define B_TILE   (256*LDS_ROW)         // 20480 B
#define STAGE_B  (A_TILE + B_TILE)     // 30720 B
#define NSTAGE   4
#define SMEM_GEMM (NSTAGE*STAGE_B)     // 122880 B

__global__ void __launch_bounds__(256, 1)
gemm_mma() {
    extern __shared__ char smem[];
    const uint32_t sb = smem_u32(smem);
    const int tid  = threadIdx.x;
    const int lane = tid & 31;
    const int wid  = tid >> 5;
    const int mwarp = wid & 1;          // 2 warps along M (64 rows each)
    const int nwarp = wid >> 1;         // 4 warps along N (64 cols each)
    const int m0 = blockIdx.y * 128;
    const int n0 = blockIdx.x * 256;

    auto load_stage = [&](int s) {
        const int kb = s * 32;
        const int tap = (kb < 256) ? 0 : 1;
        const int xcol = kb - tap * 256;
        const int rowoff = tap ? 0 : -8;
        const uint32_t base = sb + (s & (NSTAGE - 1)) * STAGE_B;
#pragma unroll
        for (int q = 0; q < 6; q++) {
            const int idx = q * 256 + tid;
            if (q < 2) {                 // A : ids 0..511
                int row = idx >> 2, c = idx & 3;
                int gm = m0 + row + rowoff;
                int gmc = (gm >= 0) ? gm : 0;
                cp_async16(base + row * LDS_ROW + c * 16,
                           g_Xh + gmc * CH + xcol + c * 8, (gm >= 0) ? 16u : 0u);
            } else {                     // B : ids 0..1023
                int i2 = idx - 512;
                int row = i2 >> 2, c = i2 & 3;
                cp_async16(base + A_TILE + row * LDS_ROW + c * 16,
                           g_Wh + (n0 + row) * KDIM + kb + c * 8, 16u);
            }
        }
    };

    float acc[4][8][4];
#pragma unroll
    for (int i = 0; i < 4; i++)
#pragma unroll
        for (int j = 0; j < 8; j++)
#pragma unroll
            for (int q = 0; q < 4; q++) acc[i][j][q] = 0.0f;

    const uint32_t a_off = (mwarp * 64 + (lane & 15)) * LDS_ROW + (lane >> 4) * 16;
    const uint32_t b_off = (nwarp * 64 + (lane & 7)) * LDS_ROW + ((lane >> 3) & 1) * 16;

    load_stage(0); CP_COMMIT();
    load_stage(1); CP_COMMIT();
    load_stage(2); CP_COMMIT();

    for (int s = 0; s < 16; s++) {
        CP_WAIT(2);                 // stage s resident (3 groups in flight)
        __syncthreads();            // all warps done reading buffer (s-1)&3
        if (s + 3 < 16) load_stage(s + 3);
        CP_COMMIT();                // empty group keeps WAIT(2) exact

        const uint32_t base = sb + (s & (NSTAGE - 1)) * STAGE_B;
#pragma unroll
        for (int kk = 0; kk < 2; kk++) {
            uint32_t aH[4][4];
#pragma unroll
            for (int mf = 0; mf < 4; mf++)
                ldsm_x4(aH[mf], base + a_off + mf * 16 * LDS_ROW + kk * 32);
#pragma unroll
            for (int nf = 0; nf < 8; nf++) {
                uint32_t b[2];
                ldsm_x2(b, base + A_TILE + b_off + nf * 8 * LDS_ROW + kk * 32);
#pragma unroll
                for (int mf = 0; mf < 4; mf++)
                    mma_f16(acc[mf][nf], aH[mf], b);
            }
        }
    }

    // ---- epilogue: +bias, activation, write gates to g_Z / g_F ----
    const int g4  = lane >> 2;            // 0..7 (row within 8)
    const int t4  = lane & 3;             // 0..3 (col pair)
    const bool isF = (n0 >= 256);
    float* dstBase = isF ? g_F : g_Z;
    const int nbias0 = n0 + nwarp * 64 + t4 * 2;
    const int nloc0  = nbias0 - (isF ? 256 : 0);

#pragma unroll
    for (int nf = 0; nf < 8; nf++) {
        const int ncol = nloc0 + nf * 8;
        const float b0 = g_biasf[nbias0 + nf * 8];
        const float b1 = g_biasf[nbias0 + nf * 8 + 1];
#pragma unroll
        for (int mf = 0; mf < 4; mf++) {
            const int m = m0 + mwarp * 64 + mf * 16 + g4;
            float v00 = acc[mf][nf][0] + b0, v01 = acc[mf][nf][1] + b1;
            float v10 = acc[mf][nf][2] + b0, v11 = acc[mf][nf][3] + b1;
            float2 o0, o1;
            if (isF) {
                o0 = make_float2(sigf(v00), sigf(v01));
                o1 = make_float2(sigf(v10), sigf(v11));
            } else {
                o0 = make_float2(v00 * sigf(1.702f * v00), v01 * sigf(1.702f * v01));
                o1 = make_float2(v10 * sigf(1.702f * v10), v11 * sigf(1.702f * v11));
            }
            *reinterpret_cast<float2*>(dstBase + m * CH + ncol)       = o0;
            *reinterpret_cast<float2*>(dstBase + (m + 8) * CH + ncol) = o1;
        }
    }
}

// ---------------------------------------------------------------------------
// Scan pass 1: per (chunk, bh), compose chunk affine (A, B)
//   per step: a = 1-f, b = f*z   (f, z already activated)
// ---------------------------------------------------------------------------
__global__ void scan1() {
    const int bh = blockIdx.x * 256 + threadIdx.x;
    const int c  = blockIdx.y;
    float A = 1.0f, B = 0.0f;
    const int tbase = c * CHUNK;
#pragma unroll 8
    for (int t = 0; t < CHUNK; t++) {
        int idx = (tbase + t) * BHTOT + bh;
        float f = g_F[idx];
        float z = g_Z[idx];
        float a = 1.0f - f;
        A *= a;
        B = fmaf(a, B, f * z);
    }
    g_cA[c * BHTOT + bh] = A;
    g_cB[c * BHTOT + bh] = B;
}

// ---------------------------------------------------------------------------
// Scan pass 2: prefix over 128 chunks, 16-wide prefetch batches
// ---------------------------------------------------------------------------
__global__ void scan2(const float* __restrict__ hidden, float* __restrict__ out) {
    const int bh = blockIdx.x * 256 + threadIdx.x;
    float h = hidden[bh];
    for (int cb = 0; cb < NCHUNK; cb += 16) {
        float A[16], Bv[16];
#pragma unroll
        for (int i = 0; i < 16; i++) {
            A[i]  = g_cA[(cb + i) * BHTOT + bh];
            Bv[i] = g_cB[(cb + i) * BHTOT + bh];
        }
#pragma unroll
        for (int i = 0; i < 16; i++) {
            g_cH[(cb + i) * BHTOT + bh] = h;
            h = fmaf(A[i], h, Bv[i]);
        }
    }
    out[SEQ * BHTOT + bh] = h;   // h_last
}

// ---------------------------------------------------------------------------
// Scan pass 3: replay each chunk, write H:  h += f*(z - h)
// ---------------------------------------------------------------------------
__global__ void scan3(float* __restrict__ out) {
    const int bh = blockIdx.x * 256 + threadIdx.x;
    const int c  = blockIdx.y;
    float h = g_cH[c * BHTOT + bh];
    const int tbase = c * CHUNK;
#pragma unroll 8
    for (int t = 0; t < CHUNK; t++) {
        int idx = (tbase + t) * BHTOT + bh;
        float f = g_F[idx];
        float z = g_Z[idx];
        h = fmaf(f, z - h, h);
        out[idx] = h;
    }
}

// ---------------------------------------------------------------------------
extern "C" void kernel_launch(void* const* d_in, const int* in_sizes, int n_in,
                              void* d_out, int out_size) {
    const float* X      = (const float*)d_in[0];
    const float* hidden = (const float*)d_in[1];
    const float* Wz     = (const float*)d_in[2];
    const float* bz     = (const float*)d_in[3];
    const float* Wf     = (const float*)d_in[4];
    const float* bf     = (const float*)d_in[5];
    float* out = (float*)d_out;

    convert_x<<<M_TOT * CH / 4 / 256, 256>>>(X);
    pack_w<<<(NDIM * KDIM + 255) / 256, 256>>>(Wz, bz, Wf, bf);

    cudaFuncSetAttribute(gemm_mma, cudaFuncAttributeMaxDynamicSharedMemorySize, SMEM_GEMM);
    gemm_mma<<<dim3(2, 256), 256, SMEM_GEMM>>>();

    scan1<<<dim3(BHTOT / 256, NCHUNK), 256>>>();
    scan2<<<BHTOT / 256, 256>>>(hidden, out);
    scan3<<<dim3(BHTOT / 256, NCHUNK), 256>>>(out);
}